// round 7
// baseline (speedup 1.0000x reference)
#include <cuda_runtime.h>
#include <cuda_bf16.h>
#include <math.h>

// ---------------- problem constants ----------------
#define NBATCH 1024      // N*M
#define TSTEPS 300
#define HID    128
#define GATES  512       // 4*HID
#define FEAT   45        // V*C
#define NCLS   60
#define NROWS  (TSTEPS*NBATCH)   // 307200 GEMM rows

// ---------------- scratch (device globals; no allocation allowed) ----------
__device__ float  g_gates[(size_t)NROWS * GATES];     // 629 MB, layer-0 gate inputs
__device__ float  g_hlast[NBATCH * HID];
__device__ float  g_weffT[FEAT * GATES];              // [f][g] fused cheb+wih0
__device__ float  g_beff0[GATES];
__device__ float  g_beff1[GATES];
__device__ float4 g_wpack0[HID * HID];                // [k][j] -> (i,f,g,o) whh0
__device__ float4 g_wpack1[HID * HID];                // [k][j] -> (i,f,g,o) whh1
__device__ float4 g_wpackih1[HID * HID];              // [k][j] -> (i,f,g,o) wih1

// skeleton edges
__constant__ int c_src[28] = {0,2,4,1,3,5,6,8,10,7,9,11,13,12,2,4,14,3,5,14,8,10,13,9,11,13,12,13};
__constant__ int c_dst[28] = {2,4,14,3,5,14,8,10,13,9,11,13,14,13,0,2,4,1,3,5,6,8,10,7,9,11,13,14};

// ---------------- f32x2 helpers (Blackwell packed fp32) ---------------------
__device__ __forceinline__ void ffma2(unsigned long long& acc,
                                      unsigned long long w2,
                                      unsigned long long h2) {
    asm("fma.rn.f32x2 %0, %1, %2, %0;" : "+l"(acc) : "l"(w2), "l"(h2));
}
__device__ __forceinline__ unsigned long long dup2(float w) {
    unsigned long long r;
    asm("mov.b64 %0, {%1, %1};" : "=l"(r) : "f"(w));
    return r;
}
__device__ __forceinline__ void unpack2(float& lo, float& hi, unsigned long long v) {
    asm("mov.b64 {%0, %1}, %2;" : "=f"(lo), "=f"(hi) : "l"(v));
}

// ---------------- precompute: L_hat, fused cheb weights, weight repacks ----
__global__ __launch_bounds__(512) void precompute_kernel(
    const float* __restrict__ w0, const float* __restrict__ w1, const float* __restrict__ chb,
    const float* __restrict__ wih0, const float* __restrict__ whh0,
    const float* __restrict__ bih0, const float* __restrict__ bhh0,
    const float* __restrict__ wih1, const float* __restrict__ whh1,
    const float* __restrict__ bih1, const float* __restrict__ bhh1)
{
    __shared__ float L[15][15];
    int tid = threadIdx.x;
    if (tid < 225) L[tid / 15][tid % 15] = 0.0f;
    __syncthreads();
    if (tid == 0) {
        for (int e = 0; e < 28; e++) L[c_dst[e]][c_src[e]] = 1.0f;
        float dinv[15];
        for (int v = 0; v < 15; v++) {
            float d = 0.f;
            for (int jj = 0; jj < 15; jj++) d += L[v][jj];
            dinv[v] = (d > 0.f) ? rsqrtf(d) : 0.f;
        }
        for (int v = 0; v < 15; v++)
            for (int jj = 0; jj < 15; jj++)
                L[v][jj] = -(dinv[v] * L[v][jj] * dinv[jj]);
    }
    __syncthreads();

    // fused cheb -> W_eff, b_eff   (thread = gate row g)
    {
        int g = tid; // 0..511
        float be = bih0[g] + bhh0[g];
        for (int v = 0; v < 15; v++)
            for (int co = 0; co < 3; co++)
                be += wih0[g * FEAT + v * 3 + co] * chb[co];
        g_beff0[g] = be;
        g_beff1[g] = bih1[g] + bhh1[g];

        for (int f = 0; f < FEAT; f++) {
            int v = f / 3, c = f - v * 3;
            float s = 0.f;
            for (int co = 0; co < 3; co++)
                s += wih0[g * FEAT + v * 3 + co] * w0[co * 3 + c];
            for (int jj = 0; jj < 15; jj++) {
                float lv = L[jj][v];
                if (lv != 0.f) {
                    for (int co = 0; co < 3; co++)
                        s += wih0[g * FEAT + jj * 3 + co] * lv * w1[co * 3 + c];
                }
            }
            g_weffT[f * GATES + g] = s;
        }
    }

    // repacks: [k][j] -> float4 (i,f,g,o)
    for (int idx = tid; idx < HID * HID; idx += 512) {
        int k = idx >> 7, j = idx & 127;
        float4 a;
        a.x = whh0[(0 * HID + j) * HID + k];
        a.y = whh0[(1 * HID + j) * HID + k];
        a.z = whh0[(2 * HID + j) * HID + k];
        a.w = whh0[(3 * HID + j) * HID + k];
        g_wpack0[k * HID + j] = a;
        a.x = whh1[(0 * HID + j) * HID + k];
        a.y = whh1[(1 * HID + j) * HID + k];
        a.z = whh1[(2 * HID + j) * HID + k];
        a.w = whh1[(3 * HID + j) * HID + k];
        g_wpack1[k * HID + j] = a;
        a.x = wih1[(0 * HID + j) * HID + k];
        a.y = wih1[(1 * HID + j) * HID + k];
        a.z = wih1[(2 * HID + j) * HID + k];
        a.w = wih1[(3 * HID + j) * HID + k];
        g_wpackih1[k * HID + j] = a;
    }
}

// ---------------- G0: gather(x1) @ W_eff^T + b_eff --------------------------
__global__ __launch_bounds__(256) void g0_gemm_kernel(const float* __restrict__ x1)
{
    __shared__ float Xs[64][FEAT + 1];
    __shared__ float Ws[FEAT][128];
    __shared__ float Bs[128];
    int ct = blockIdx.x;            // 0..3
    int r0 = blockIdx.y * 64;
    int tid = threadIdx.x;

    for (int idx = tid; idx < FEAT * 128; idx += 256) {
        int k = idx >> 7, c = idx & 127;
        Ws[k][c] = g_weffT[k * GATES + ct * 128 + c];
    }
    if (tid < 128) Bs[tid] = g_beff0[ct * 128 + tid];
    for (int idx = tid; idx < FEAT * 64; idx += 256) {
        int f = idx >> 6, i = idx & 63;
        int r = r0 + i;
        int t = r >> 10, b = r & 1023;
        int n = b >> 1, m = b & 1;
        int v = f / 3, c = f - v * 3;
        Xs[i][f] = x1[(((size_t)(n * 3 + c) * 300 + t) * 15 + v) * 2 + m];
    }
    __syncthreads();

    int ty = tid >> 4, tx = tid & 15;
    float acc[4][8];
#pragma unroll
    for (int a = 0; a < 4; a++)
#pragma unroll
        for (int b = 0; b < 8; b++) acc[a][b] = 0.f;

#pragma unroll 5
    for (int k = 0; k < FEAT; k++) {
        float xv[4], wv[8];
#pragma unroll
        for (int ii = 0; ii < 4; ii++) xv[ii] = Xs[ty * 4 + ii][k];
#pragma unroll
        for (int jj = 0; jj < 8; jj++) wv[jj] = Ws[k][tx + jj * 16];
#pragma unroll
        for (int ii = 0; ii < 4; ii++)
#pragma unroll
            for (int jj = 0; jj < 8; jj++)
                acc[ii][jj] = fmaf(xv[ii], wv[jj], acc[ii][jj]);
    }
#pragma unroll
    for (int ii = 0; ii < 4; ii++) {
        size_t rowbase = (size_t)(r0 + ty * 4 + ii) * GATES + ct * 128;
#pragma unroll
        for (int jj = 0; jj < 8; jj++) {
            int c = tx + jj * 16;
            g_gates[rowbase + c] = acc[ii][jj] + Bs[c];
        }
    }
}

// ---------------- fused 2-layer LSTM (batch-parallel, f32x2) ----------------
// 128 CTAs x 256 threads. CTA owns 8 batch rows. Thread = (j = tid&127,
// half = tid>>7) and owns hidden j for batches 4*half .. 4*half+3 (two f32x2
// lanes). h kept in smem transposed [k][b] (stride 10) so h loads are
// broadcast LDS.64.
__device__ __forceinline__ float fsigm(float x) { return 1.f / (1.f + __expf(-x)); }
__device__ __forceinline__ float ftanh(float x) {
    return 1.f - 2.f / (__expf(2.f * x) + 1.f);
}

#define HSTRIDE 10

__global__ __launch_bounds__(256) void fused_lstm_kernel()
{
    __shared__ float h0sm[HID * HSTRIDE];
    __shared__ float h1sm[HID * HSTRIDE];
    int tid  = threadIdx.x;
    int j    = tid & 127;
    int half = tid >> 7;          // 0 or 1
    int bofs = half * 4;          // first owned batch within CTA
    int b0   = blockIdx.x * 8;    // CTA batch base

    for (int idx = tid; idx < HID * HSTRIDE; idx += 256) {
        h0sm[idx] = 0.f;
        h1sm[idx] = 0.f;
    }
    float c0[4] = {0.f, 0.f, 0.f, 0.f};
    float c1[4] = {0.f, 0.f, 0.f, 0.f};
    float bi1 = g_beff1[0 * HID + j];
    float bf1 = g_beff1[1 * HID + j];
    float bg1 = g_beff1[2 * HID + j];
    float bo1 = g_beff1[3 * HID + j];
    __syncthreads();

    for (int t = 0; t < TSTEPS; t++) {
        // ---- phase A: both recurrences from old h ----
        // acc[layer][gate][pair]
        unsigned long long a0[4][2], a1[4][2];
#pragma unroll
        for (int g = 0; g < 4; g++) {
            a0[g][0] = 0ull; a0[g][1] = 0ull;
            a1[g][0] = 0ull; a1[g][1] = 0ull;
        }
#pragma unroll 4
        for (int k = 0; k < HID; k++) {
            float4 w0v = g_wpack0[k * HID + j];
            float4 w1v = g_wpack1[k * HID + j];
            unsigned long long h0a = *(const unsigned long long*)&h0sm[k * HSTRIDE + bofs];
            unsigned long long h0b = *(const unsigned long long*)&h0sm[k * HSTRIDE + bofs + 2];
            unsigned long long h1a = *(const unsigned long long*)&h1sm[k * HSTRIDE + bofs];
            unsigned long long h1b = *(const unsigned long long*)&h1sm[k * HSTRIDE + bofs + 2];
            unsigned long long wd;
            wd = dup2(w0v.x); ffma2(a0[0][0], wd, h0a); ffma2(a0[0][1], wd, h0b);
            wd = dup2(w0v.y); ffma2(a0[1][0], wd, h0a); ffma2(a0[1][1], wd, h0b);
            wd = dup2(w0v.z); ffma2(a0[2][0], wd, h0a); ffma2(a0[2][1], wd, h0b);
            wd = dup2(w0v.w); ffma2(a0[3][0], wd, h0a); ffma2(a0[3][1], wd, h0b);
            wd = dup2(w1v.x); ffma2(a1[0][0], wd, h1a); ffma2(a1[0][1], wd, h1b);
            wd = dup2(w1v.y); ffma2(a1[1][0], wd, h1a); ffma2(a1[1][1], wd, h1b);
            wd = dup2(w1v.z); ffma2(a1[2][0], wd, h1a); ffma2(a1[2][1], wd, h1b);
            wd = dup2(w1v.w); ffma2(a1[3][0], wd, h1a); ffma2(a1[3][1], wd, h1b);
        }
        __syncthreads();   // all reads of old h0/h1 done

        // ---- phase B: layer-0 cell update (gates from gmem + acc0) ----
        {
            float gA[4][4];   // [gate][batch]
#pragma unroll
            for (int g = 0; g < 4; g++) {
                unpack2(gA[g][0], gA[g][1], a0[g][0]);
                unpack2(gA[g][2], gA[g][3], a0[g][1]);
            }
            const float* __restrict__ gb =
                g_gates + ((size_t)t * NBATCH + b0 + bofs) * GATES;
            float hnew[4];
#pragma unroll
            for (int b = 0; b < 4; b++) {
                float gi = gb[b * GATES + 0 * HID + j] + gA[0][b];
                float gf = gb[b * GATES + 1 * HID + j] + gA[1][b];
                float gg = gb[b * GATES + 2 * HID + j] + gA[2][b];
                float go = gb[b * GATES + 3 * HID + j] + gA[3][b];
                c0[b] = fsigm(gf) * c0[b] + fsigm(gi) * ftanh(gg);
                hnew[b] = fsigm(go) * ftanh(c0[b]);
            }
            *(float2*)&h0sm[j * HSTRIDE + bofs]     = make_float2(hnew[0], hnew[1]);
            *(float2*)&h0sm[j * HSTRIDE + bofs + 2] = make_float2(hnew[2], hnew[3]);
        }
        __syncthreads();   // h0 updated, visible to all

        // ---- phase C: layer-1 input GEMM from fresh h0, then cell update ----
#pragma unroll 4
        for (int k = 0; k < HID; k++) {
            float4 wv = g_wpackih1[k * HID + j];
            unsigned long long ha = *(const unsigned long long*)&h0sm[k * HSTRIDE + bofs];
            unsigned long long hb = *(const unsigned long long*)&h0sm[k * HSTRIDE + bofs + 2];
            unsigned long long wd;
            wd = dup2(wv.x); ffma2(a1[0][0], wd, ha); ffma2(a1[0][1], wd, hb);
            wd = dup2(wv.y); ffma2(a1[1][0], wd, ha); ffma2(a1[1][1], wd, hb);
            wd = dup2(wv.z); ffma2(a1[2][0], wd, ha); ffma2(a1[2][1], wd, hb);
            wd = dup2(wv.w); ffma2(a1[3][0], wd, ha); ffma2(a1[3][1], wd, hb);
        }
        {
            float gA[4][4];
#pragma unroll
            for (int g = 0; g < 4; g++) {
                unpack2(gA[g][0], gA[g][1], a1[g][0]);
                unpack2(gA[g][2], gA[g][3], a1[g][1]);
            }
            float hnew[4];
#pragma unroll
            for (int b = 0; b < 4; b++) {
                float gi = gA[0][b] + bi1;
                float gf = gA[1][b] + bf1;
                float gg = gA[2][b] + bg1;
                float go = gA[3][b] + bo1;
                c1[b] = fsigm(gf) * c1[b] + fsigm(gi) * ftanh(gg);
                hnew[b] = fsigm(go) * ftanh(c1[b]);
            }
            *(float2*)&h1sm[j * HSTRIDE + bofs]     = make_float2(hnew[0], hnew[1]);
            *(float2*)&h1sm[j * HSTRIDE + bofs + 2] = make_float2(hnew[2], hnew[3]);
            if (t == TSTEPS - 1) {
#pragma unroll
                for (int b = 0; b < 4; b++)
                    g_hlast[(b0 + bofs + b) * HID + j] = hnew[b];
            }
        }
        __syncthreads();   // h1 updated before next step's phase A
    }
}

// ---------------- FC + softmax ---------------------------------------------
__global__ __launch_bounds__(64) void fc_softmax_kernel(
    const float* __restrict__ fcw, const float* __restrict__ fcb, float* __restrict__ out)
{
    int row = blockIdx.x;
    int tid = threadIdx.x;
    __shared__ float hrow[HID];
    __shared__ float red[64];
    hrow[tid]      = g_hlast[row * HID + tid];
    hrow[tid + 64] = g_hlast[row * HID + 64 + tid];
    __syncthreads();

    float logit = 0.f;
    if (tid < NCLS) {
        logit = fcb[tid];
#pragma unroll 8
        for (int k = 0; k < HID; k++)
            logit = fmaf(hrow[k], fcw[tid * HID + k], logit);
    }
    red[tid] = (tid < NCLS) ? logit : -INFINITY;
    __syncthreads();
    for (int s = 32; s > 0; s >>= 1) {
        if (tid < s) red[tid] = fmaxf(red[tid], red[tid + s]);
        __syncthreads();
    }
    float mx = red[0];
    __syncthreads();
    float e = (tid < NCLS) ? expf(logit - mx) : 0.f;
    red[tid] = e;
    __syncthreads();
    for (int s = 32; s > 0; s >>= 1) {
        if (tid < s) red[tid] += red[tid + s];
        __syncthreads();
    }
    float inv = 1.f / red[0];
    if (tid < NCLS) out[row * NCLS + tid] = e * inv;
}

// ---------------- launch ----------------------------------------------------
extern "C" void kernel_launch(void* const* d_in, const int* in_sizes, int n_in,
                              void* d_out, int out_size)
{
    const float* x1   = (const float*)d_in[0];
    const float* w0   = (const float*)d_in[2];
    const float* w1   = (const float*)d_in[3];
    const float* chb  = (const float*)d_in[4];
    const float* wih0 = (const float*)d_in[5];
    const float* whh0 = (const float*)d_in[6];
    const float* bih0 = (const float*)d_in[7];
    const float* bhh0 = (const float*)d_in[8];
    const float* wih1 = (const float*)d_in[9];
    const float* whh1 = (const float*)d_in[10];
    const float* bih1 = (const float*)d_in[11];
    const float* bhh1 = (const float*)d_in[12];
    const float* fcw  = (const float*)d_in[13];
    const float* fcb  = (const float*)d_in[14];
    float* out = (float*)d_out;

    precompute_kernel<<<1, 512>>>(w0, w1, chb, wih0, whh0, bih0, bhh0,
                                  wih1, whh1, bih1, bhh1);
    g0_gemm_kernel<<<dim3(4, NROWS / 64), 256>>>(x1);
    fused_lstm_kernel<<<NBATCH / 8, 256>>>();
    fc_softmax_kernel<<<NBATCH, 64>>>(fcw, fcb, out);
}

// round 8
// speedup vs baseline: 1.6032x; 1.6032x over previous
#include <cuda_runtime.h>
#include <cuda_bf16.h>
#include <math.h>

// ---------------- problem constants ----------------
#define NBATCH 1024      // N*M
#define TSTEPS 300
#define HID    128
#define GATES  512       // 4*HID
#define FEAT   45        // V*C
#define NCLS   60
#define NROWS  (TSTEPS*NBATCH)   // 307200 GEMM rows

// ---------------- scratch (device globals; no allocation allowed) ----------
__device__ float  g_gates[(size_t)NROWS * GATES];     // 629 MB, layer-0 gate inputs
__device__ float  g_hlast[NBATCH * HID];
__device__ float  g_weffT[FEAT * GATES];              // [f][g] fused cheb+wih0
__device__ float  g_beff0[GATES];
__device__ float  g_beff1[GATES];
__device__ float4 g_wpack0[HID * HID];                // [k][j] -> (i,f,g,o) whh0
__device__ float4 g_wpack1[HID * HID];                // [k][j] -> (i,f,g,o) whh1
__device__ float4 g_wpackih1[HID * HID];              // [k][j] -> (i,f,g,o) wih1

// skeleton edges
__constant__ int c_src[28] = {0,2,4,1,3,5,6,8,10,7,9,11,13,12,2,4,14,3,5,14,8,10,13,9,11,13,12,13};
__constant__ int c_dst[28] = {2,4,14,3,5,14,8,10,13,9,11,13,14,13,0,2,4,1,3,5,6,8,10,7,9,11,13,14};

// ---------------- precompute: L_hat, fused cheb weights, weight repacks ----
__global__ __launch_bounds__(512) void precompute_kernel(
    const float* __restrict__ w0, const float* __restrict__ w1, const float* __restrict__ chb,
    const float* __restrict__ wih0, const float* __restrict__ whh0,
    const float* __restrict__ bih0, const float* __restrict__ bhh0,
    const float* __restrict__ wih1, const float* __restrict__ whh1,
    const float* __restrict__ bih1, const float* __restrict__ bhh1)
{
    __shared__ float L[15][15];
    int tid = threadIdx.x;
    if (tid < 225) L[tid / 15][tid % 15] = 0.0f;
    __syncthreads();
    if (tid == 0) {
        for (int e = 0; e < 28; e++) L[c_dst[e]][c_src[e]] = 1.0f;
        float dinv[15];
        for (int v = 0; v < 15; v++) {
            float d = 0.f;
            for (int jj = 0; jj < 15; jj++) d += L[v][jj];
            dinv[v] = (d > 0.f) ? rsqrtf(d) : 0.f;
        }
        for (int v = 0; v < 15; v++)
            for (int jj = 0; jj < 15; jj++)
                L[v][jj] = -(dinv[v] * L[v][jj] * dinv[jj]);
    }
    __syncthreads();

    // fused cheb -> W_eff, b_eff   (thread = gate row g)
    {
        int g = tid; // 0..511
        float be = bih0[g] + bhh0[g];
        for (int v = 0; v < 15; v++)
            for (int co = 0; co < 3; co++)
                be += wih0[g * FEAT + v * 3 + co] * chb[co];
        g_beff0[g] = be;
        g_beff1[g] = bih1[g] + bhh1[g];

        for (int f = 0; f < FEAT; f++) {
            int v = f / 3, c = f - v * 3;
            float s = 0.f;
            for (int co = 0; co < 3; co++)
                s += wih0[g * FEAT + v * 3 + co] * w0[co * 3 + c];
            for (int jj = 0; jj < 15; jj++) {
                float lv = L[jj][v];
                if (lv != 0.f) {
                    for (int co = 0; co < 3; co++)
                        s += wih0[g * FEAT + jj * 3 + co] * lv * w1[co * 3 + c];
                }
            }
            g_weffT[f * GATES + g] = s;
        }
    }

    // repacks: [k][j] -> float4 (i,f,g,o)
    for (int idx = tid; idx < HID * HID; idx += 512) {
        int k = idx >> 7, j = idx & 127;
        float4 a;
        a.x = whh0[(0 * HID + j) * HID + k];
        a.y = whh0[(1 * HID + j) * HID + k];
        a.z = whh0[(2 * HID + j) * HID + k];
        a.w = whh0[(3 * HID + j) * HID + k];
        g_wpack0[k * HID + j] = a;
        a.x = whh1[(0 * HID + j) * HID + k];
        a.y = whh1[(1 * HID + j) * HID + k];
        a.z = whh1[(2 * HID + j) * HID + k];
        a.w = whh1[(3 * HID + j) * HID + k];
        g_wpack1[k * HID + j] = a;
        a.x = wih1[(0 * HID + j) * HID + k];
        a.y = wih1[(1 * HID + j) * HID + k];
        a.z = wih1[(2 * HID + j) * HID + k];
        a.w = wih1[(3 * HID + j) * HID + k];
        g_wpackih1[k * HID + j] = a;
    }
}

// ---------------- G0: gather(x1) @ W_eff^T + b_eff --------------------------
__global__ __launch_bounds__(256) void g0_gemm_kernel(const float* __restrict__ x1)
{
    __shared__ float Xs[64][FEAT + 1];
    __shared__ float Ws[FEAT][128];
    __shared__ float Bs[128];
    int ct = blockIdx.x;            // 0..3
    int r0 = blockIdx.y * 64;
    int tid = threadIdx.x;

    for (int idx = tid; idx < FEAT * 128; idx += 256) {
        int k = idx >> 7, c = idx & 127;
        Ws[k][c] = g_weffT[k * GATES + ct * 128 + c];
    }
    if (tid < 128) Bs[tid] = g_beff0[ct * 128 + tid];
    for (int idx = tid; idx < FEAT * 64; idx += 256) {
        int f = idx >> 6, i = idx & 63;
        int r = r0 + i;
        int t = r >> 10, b = r & 1023;
        int n = b >> 1, m = b & 1;
        int v = f / 3, c = f - v * 3;
        Xs[i][f] = x1[(((size_t)(n * 3 + c) * 300 + t) * 15 + v) * 2 + m];
    }
    __syncthreads();

    int ty = tid >> 4, tx = tid & 15;
    float acc[4][8];
#pragma unroll
    for (int a = 0; a < 4; a++)
#pragma unroll
        for (int b = 0; b < 8; b++) acc[a][b] = 0.f;

#pragma unroll 5
    for (int k = 0; k < FEAT; k++) {
        float xv[4], wv[8];
#pragma unroll
        for (int ii = 0; ii < 4; ii++) xv[ii] = Xs[ty * 4 + ii][k];
#pragma unroll
        for (int jj = 0; jj < 8; jj++) wv[jj] = Ws[k][tx + jj * 16];
#pragma unroll
        for (int ii = 0; ii < 4; ii++)
#pragma unroll
            for (int jj = 0; jj < 8; jj++)
                acc[ii][jj] = fmaf(xv[ii], wv[jj], acc[ii][jj]);
    }
#pragma unroll
    for (int ii = 0; ii < 4; ii++) {
        size_t rowbase = (size_t)(r0 + ty * 4 + ii) * GATES + ct * 128;
#pragma unroll
        for (int jj = 0; jj < 8; jj++) {
            int c = tx + jj * 16;
            g_gates[rowbase + c] = acc[ii][jj] + Bs[c];
        }
    }
}

// ---------------- fused 2-layer LSTM (batch-parallel) -----------------------
// 128 CTAs x 256 threads. CTA owns 8 batch rows. Thread = (j = tid&127,
// half = tid>>7); owns hidden j for batches 4*half .. 4*half+3. Two warps
// per SMSP hide LDG/LDS latency. Plain scalar FFMA (proven numerics).
// Per step:
//   A: acc0 = Whh0 . h0_old ; acc1 = Whh1 . h1_old     (reads old h's)
//   B: h0_new = lstm0(gates_gmem + acc0)               (writes h0sm)
//   C: g1 += Wih1 . h0_new ; h1_new = lstm1(g1)
__device__ __forceinline__ float fsigm(float x) { return 1.f / (1.f + __expf(-x)); }
__device__ __forceinline__ float ftanh(float x) {
    return 1.f - 2.f / (__expf(2.f * x) + 1.f);
}

__global__ __launch_bounds__(256) void fused_lstm_kernel()
{
    __shared__ float h0sm[8][HID];
    __shared__ float h1sm[8][HID];
    int tid  = threadIdx.x;
    int j    = tid & 127;
    int half = tid >> 7;          // 0 or 1 (uniform per warp)
    int bofs = half * 4;          // first owned batch within CTA
    int b0   = blockIdx.x * 8;    // CTA batch base

    for (int idx = tid; idx < 8 * HID; idx += 256) {
        ((float*)h0sm)[idx] = 0.f;
        ((float*)h1sm)[idx] = 0.f;
    }
    float c0[4] = {0.f, 0.f, 0.f, 0.f};
    float c1[4] = {0.f, 0.f, 0.f, 0.f};
    float bi1 = g_beff1[0 * HID + j];
    float bf1 = g_beff1[1 * HID + j];
    float bg1 = g_beff1[2 * HID + j];
    float bo1 = g_beff1[3 * HID + j];
    __syncthreads();

    for (int t = 0; t < TSTEPS; t++) {
        // ---- phase A: both recurrences from old h ----
        float ai0[4], af0[4], ag0[4], ao0[4];
        float ai1[4], af1[4], ag1[4], ao1[4];
#pragma unroll
        for (int b = 0; b < 4; b++) {
            ai0[b] = 0.f; af0[b] = 0.f; ag0[b] = 0.f; ao0[b] = 0.f;
            ai1[b] = 0.f; af1[b] = 0.f; ag1[b] = 0.f; ao1[b] = 0.f;
        }
#pragma unroll 4
        for (int k = 0; k < HID; k++) {
            float4 w0v = g_wpack0[k * HID + j];
            float4 w1v = g_wpack1[k * HID + j];
#pragma unroll
            for (int b = 0; b < 4; b++) {
                float hv0 = h0sm[bofs + b][k];
                ai0[b] = fmaf(w0v.x, hv0, ai0[b]);
                af0[b] = fmaf(w0v.y, hv0, af0[b]);
                ag0[b] = fmaf(w0v.z, hv0, ag0[b]);
                ao0[b] = fmaf(w0v.w, hv0, ao0[b]);
                float hv1 = h1sm[bofs + b][k];
                ai1[b] = fmaf(w1v.x, hv1, ai1[b]);
                af1[b] = fmaf(w1v.y, hv1, af1[b]);
                ag1[b] = fmaf(w1v.z, hv1, ag1[b]);
                ao1[b] = fmaf(w1v.w, hv1, ao1[b]);
            }
        }
        __syncthreads();   // all reads of old h0/h1 done

        // ---- phase B: layer-0 cell update (gates from gmem + acc0) ----
        {
            const float* __restrict__ gb =
                g_gates + ((size_t)t * NBATCH + b0 + bofs) * GATES;
#pragma unroll
            for (int b = 0; b < 4; b++) {
                float gi = gb[b * GATES + 0 * HID + j] + ai0[b];
                float gf = gb[b * GATES + 1 * HID + j] + af0[b];
                float gg = gb[b * GATES + 2 * HID + j] + ag0[b];
                float go = gb[b * GATES + 3 * HID + j] + ao0[b];
                c0[b] = fsigm(gf) * c0[b] + fsigm(gi) * ftanh(gg);
                h0sm[bofs + b][j] = fsigm(go) * ftanh(c0[b]);
            }
        }
        __syncthreads();   // h0 updated, visible to all

        // ---- phase C: layer-1 input GEMM from fresh h0, then cell update ----
#pragma unroll 4
        for (int k = 0; k < HID; k++) {
            float4 wv = g_wpackih1[k * HID + j];
#pragma unroll
            for (int b = 0; b < 4; b++) {
                float hv = h0sm[bofs + b][k];
                ai1[b] = fmaf(wv.x, hv, ai1[b]);
                af1[b] = fmaf(wv.y, hv, af1[b]);
                ag1[b] = fmaf(wv.z, hv, ag1[b]);
                ao1[b] = fmaf(wv.w, hv, ao1[b]);
            }
        }
#pragma unroll
        for (int b = 0; b < 4; b++) {
            float gi = ai1[b] + bi1;
            float gf = af1[b] + bf1;
            float gg = ag1[b] + bg1;
            float go = ao1[b] + bo1;
            c1[b] = fsigm(gf) * c1[b] + fsigm(gi) * ftanh(gg);
            float h = fsigm(go) * ftanh(c1[b]);
            h1sm[bofs + b][j] = h;
            if (t == TSTEPS - 1) g_hlast[(b0 + bofs + b) * HID + j] = h;
        }
        __syncthreads();   // h1 updated before next step's phase A
    }
}

// ---------------- FC + softmax ---------------------------------------------
__global__ __launch_bounds__(64) void fc_softmax_kernel(
    const float* __restrict__ fcw, const float* __restrict__ fcb, float* __restrict__ out)
{
    int row = blockIdx.x;
    int tid = threadIdx.x;
    __shared__ float hrow[HID];
    __shared__ float red[64];
    hrow[tid]      = g_hlast[row * HID + tid];
    hrow[tid + 64] = g_hlast[row * HID + 64 + tid];
    __syncthreads();

    float logit = 0.f;
    if (tid < NCLS) {
        logit = fcb[tid];
#pragma unroll 8
        for (int k = 0; k < HID; k++)
            logit = fmaf(hrow[k], fcw[tid * HID + k], logit);
    }
    red[tid] = (tid < NCLS) ? logit : -INFINITY;
    __syncthreads();
    for (int s = 32; s > 0; s >>= 1) {
        if (tid < s) red[tid] = fmaxf(red[tid], red[tid + s]);
        __syncthreads();
    }
    float mx = red[0];
    __syncthreads();
    float e = (tid < NCLS) ? expf(logit - mx) : 0.f;
    red[tid] = e;
    __syncthreads();
    for (int s = 32; s > 0; s >>= 1) {
        if (tid < s) red[tid] += red[tid + s];
        __syncthreads();
    }
    float inv = 1.f / red[0];
    if (tid < NCLS) out[row * NCLS + tid] = e * inv;
}

// ---------------- launch ----------------------------------------------------
extern "C" void kernel_launch(void* const* d_in, const int* in_sizes, int n_in,
                              void* d_out, int out_size)
{
    const float* x1   = (const float*)d_in[0];
    const float* w0   = (const float*)d_in[2];
    const float* w1   = (const float*)d_in[3];
    const float* chb  = (const float*)d_in[4];
    const float* wih0 = (const float*)d_in[5];
    const float* whh0 = (const float*)d_in[6];
    const float* bih0 = (const float*)d_in[7];
    const float* bhh0 = (const float*)d_in[8];
    const float* wih1 = (const float*)d_in[9];
    const float* whh1 = (const float*)d_in[10];
    const float* bih1 = (const float*)d_in[11];
    const float* bhh1 = (const float*)d_in[12];
    const float* fcw  = (const float*)d_in[13];
    const float* fcb  = (const float*)d_in[14];
    float* out = (float*)d_out;

    precompute_kernel<<<1, 512>>>(w0, w1, chb, wih0, whh0, bih0, bhh0,
                                  wih1, whh1, bih1, bhh1);
    g0_gemm_kernel<<<dim3(4, NROWS / 64), 256>>>(x1);
    fused_lstm_kernel<<<NBATCH / 8, 256>>>();
    fc_softmax_kernel<<<NBATCH, 64>>>(fcw, fcb, out);
}